// round 9
// baseline (speedup 1.0000x reference)
#include <cuda_runtime.h>
#include <math.h>
#include <stdint.h>

#define D_MODEL 1024
#define D_HID   256
#define N_EXP   64
#define NTOK    16384

// ---------------- device scratch (static globals: allowed) ----------------
__device__ float g_H[(size_t)NTOK * D_HID];       // hidden activations
__device__ float g_W1t_hi[D_HID * D_MODEL];       // W1^T split, [h][d]
__device__ float g_W1t_lo[D_HID * D_MODEL];
__device__ float g_W2t_hi[N_EXP * D_HID];         // W2^T split, [e][k]
__device__ float g_W2t_lo[N_EXP * D_HID];
__device__ float g_W2t_f32[N_EXP * D_HID];        // W2^T full fp32 (repair path)

// ---------------- helpers ----------------
__device__ __forceinline__ uint32_t smem_u32(const void* p) {
    uint32_t a;
    asm("{ .reg .u64 t; cvta.to.shared.u64 t, %1; cvt.u32.u64 %0, t; }" : "=r"(a) : "l"(p));
    return a;
}
__device__ __forceinline__ float tf32_rn(float x) {
    uint32_t u;
    asm("cvt.rna.tf32.f32 %0, %1;" : "=r"(u) : "f"(x));
    return __uint_as_float(u);
}
__device__ __forceinline__ void cp16(uint32_t saddr, const void* gsrc) {
    asm volatile("cp.async.cg.shared.global [%0], [%1], 16;" :: "r"(saddr), "l"(gsrc) : "memory");
}
#define CP_COMMIT() asm volatile("cp.async.commit_group;" ::: "memory")
#define CP_WAIT0()  asm volatile("cp.async.wait_group 0;" ::: "memory")
#define CP_WAIT1()  asm volatile("cp.async.wait_group 1;" ::: "memory")

// m16n8k8 tf32 mma: D(f32) += A(tf32) * B(tf32)
__device__ __forceinline__ void mma_tf32(float* c, const float* a, float b0, float b1) {
    asm volatile(
        "mma.sync.aligned.m16n8k8.row.col.f32.tf32.tf32.f32 "
        "{%0,%1,%2,%3}, {%4,%5,%6,%7}, {%8,%9}, {%0,%1,%2,%3};"
        : "+f"(c[0]), "+f"(c[1]), "+f"(c[2]), "+f"(c[3])
        : "r"(__float_as_uint(a[0])), "r"(__float_as_uint(a[1])),
          "r"(__float_as_uint(a[2])), "r"(__float_as_uint(a[3])),
          "r"(__float_as_uint(b0)),  "r"(__float_as_uint(b1)));
}

// =============================================================================
// prep: split W1 -> W1t_hi/lo (transposed, K-major), W2 -> W2t_hi/lo + fp32 copy
// =============================================================================
__global__ void prep_kernel(const float* __restrict__ W1, const float* __restrict__ W2) {
    int i = blockIdx.x * 256 + threadIdx.x;
    if (i < D_MODEL * D_HID) {
        int d = i >> 8, h = i & 255;
        float w = W1[i];
        float hi = tf32_rn(w);
        g_W1t_hi[h * D_MODEL + d] = hi;
        g_W1t_lo[h * D_MODEL + d] = tf32_rn(w - hi);
    } else {
        int j = i - D_MODEL * D_HID;
        if (j < D_HID * N_EXP) {
            int k = j >> 6, e = j & 63;
            float w = W2[j];
            float hi = tf32_rn(w);
            g_W2t_hi[e * D_HID + k]  = hi;
            g_W2t_lo[e * D_HID + k]  = tf32_rn(w - hi);
            g_W2t_f32[e * D_HID + k] = w;
        }
    }
}

// =============================================================================
// GEMM1: H = tanh(X @ W1 + b1). mma.sync tf32 3-term split.
// CTA 256 thr, tile M=128 N=256 K-chunk=32, double-buffered, pad-36 rows.
//   A buf b: [b*36864]  hi 128x36, lo at +18432
//   B buf b: [73728 + b*73728] hi 256x36, lo at +36864
// =============================================================================
#define G1_SMEM 221184

__device__ __forceinline__ void g1_ldX(float4* xa, const float* X, int m0,
                                       int tid, int c) {
    const int kt = c * 32;
#pragma unroll
    for (int i = 0; i < 4; i++) {
        int q = tid + i * 256;
        xa[i] = *(const float4*)(X + (size_t)(m0 + (q >> 3)) * D_MODEL + kt + (q & 7) * 4);
    }
}
__device__ __forceinline__ void g1_stsX(char* sm, const float4* xa, int tid, int b) {
    char* A = sm + b * 36864;
#pragma unroll
    for (int i = 0; i < 4; i++) {
        int q = tid + i * 256;
        int off = (q >> 3) * 144 + (q & 7) * 16;
        float4 hi, lo;
        hi.x = tf32_rn(xa[i].x); lo.x = tf32_rn(xa[i].x - hi.x);
        hi.y = tf32_rn(xa[i].y); lo.y = tf32_rn(xa[i].y - hi.y);
        hi.z = tf32_rn(xa[i].z); lo.z = tf32_rn(xa[i].z - hi.z);
        hi.w = tf32_rn(xa[i].w); lo.w = tf32_rn(xa[i].w - hi.w);
        *(float4*)(A + off)         = hi;
        *(float4*)(A + 18432 + off) = lo;
    }
}
__device__ __forceinline__ void g1_loadB(uint32_t sb, int tid, int c, int b) {
    const int kt = c * 32;
    const uint32_t B = sb + 73728 + b * 73728;
#pragma unroll
    for (int i = 0; i < 8; i++) {
        int q = tid + i * 256;
        int n = q >> 3, c4 = q & 7;
        uint32_t off = n * 144 + c4 * 16;
        cp16(B + off,         g_W1t_hi + (size_t)n * D_MODEL + kt + c4 * 4);
        cp16(B + 36864 + off, g_W1t_lo + (size_t)n * D_MODEL + kt + c4 * 4);
    }
}

__global__ __launch_bounds__(256, 1)
void gemm1_mma(const float* __restrict__ X, const float* __restrict__ b1) {
    extern __shared__ char sm[];
    __shared__ float b1s[256];
    const uint32_t sb = smem_u32(sm);
    const int tid = threadIdx.x;
    const int wid = tid >> 5, lane = tid & 31;
    const int m0 = blockIdx.x * 128;
    const int wm = wid >> 2, wn = wid & 3;       // warp tile 64x64 in 2x4 grid
    const int g = lane >> 2, t = lane & 3;

    b1s[tid] = b1[tid];

    float acc[4][8][4];
#pragma unroll
    for (int mt = 0; mt < 4; mt++)
#pragma unroll
        for (int nt = 0; nt < 8; nt++)
#pragma unroll
            for (int k = 0; k < 4; k++) acc[mt][nt][k] = 0.0f;

    float4 xa[4];
    g1_ldX(xa, X, m0, tid, 0);
    g1_stsX(sm, xa, tid, 0);
    g1_loadB(sb, tid, 0, 0);
    CP_COMMIT();

    for (int c = 0; c < 32; c++) {
        const int b = c & 1;
        if (c < 31) {
            g1_ldX(xa, X, m0, tid, c + 1);       // LDG in flight during compute
            g1_loadB(sb, tid, c + 1, b ^ 1);
            CP_COMMIT();
            CP_WAIT1();
        } else {
            CP_WAIT0();
        }
        __syncthreads();

        const float* Ahi = (const float*)(sm + b * 36864);
        const float* Alo = Ahi + 4608;
        const float* Bhi = (const float*)(sm + 73728 + b * 73728);
        const float* Blo = Bhi + 9216;

#pragma unroll
        for (int ks = 0; ks < 4; ks++) {
            const int kc = ks * 8 + t;
            float ah[4][4], al[4][4];
#pragma unroll
            for (int mt = 0; mt < 4; mt++) {
                int r = wm * 64 + mt * 16 + g;
                ah[mt][0] = Ahi[r * 36 + kc];
                ah[mt][1] = Ahi[(r + 8) * 36 + kc];
                ah[mt][2] = Ahi[r * 36 + kc + 4];
                ah[mt][3] = Ahi[(r + 8) * 36 + kc + 4];
                al[mt][0] = Alo[r * 36 + kc];
                al[mt][1] = Alo[(r + 8) * 36 + kc];
                al[mt][2] = Alo[r * 36 + kc + 4];
                al[mt][3] = Alo[(r + 8) * 36 + kc + 4];
            }
#pragma unroll
            for (int nt = 0; nt < 8; nt++) {
                int n = wn * 64 + nt * 8 + g;
                float bh0 = Bhi[n * 36 + kc], bh1 = Bhi[n * 36 + kc + 4];
                float bl0 = Blo[n * 36 + kc], bl1 = Blo[n * 36 + kc + 4];
#pragma unroll
                for (int mt = 0; mt < 4; mt++) {
                    mma_tf32(acc[mt][nt], ah[mt], bh0, bh1);
                    mma_tf32(acc[mt][nt], al[mt], bh0, bh1);
                    mma_tf32(acc[mt][nt], ah[mt], bl0, bl1);
                }
            }
        }
        __syncthreads();
        if (c < 31) g1_stsX(sm, xa, tid, b ^ 1);  // split+STS after compute
    }

    // epilogue: +b1, tanh, store
#pragma unroll
    for (int mt = 0; mt < 4; mt++) {
        int r0 = m0 + wm * 64 + mt * 16 + g;
#pragma unroll
        for (int nt = 0; nt < 8; nt++) {
            int col = wn * 64 + nt * 8 + 2 * t;
            float2 v0, v1;
            v0.x = tanhf(acc[mt][nt][0] + b1s[col]);
            v0.y = tanhf(acc[mt][nt][1] + b1s[col + 1]);
            v1.x = tanhf(acc[mt][nt][2] + b1s[col]);
            v1.y = tanhf(acc[mt][nt][3] + b1s[col + 1]);
            *(float2*)(g_H + (size_t)r0 * D_HID + col)       = v0;
            *(float2*)(g_H + (size_t)(r0 + 8) * D_HID + col) = v1;
        }
    }
}

// =============================================================================
// GEMM2: logits = H @ W2 + b2 (tf32 3-term) + fused top-2 gating.
// Near-tie tokens (gap < 2e-4) are repaired by recomputing THE WHOLE CHAIN
// (h from X@W1, then logits) in fp64 — removes the tf32 H error that made
// the R7 fp32-from-g_H repair a no-op.
//   A buf b: [b*36864] hi 128x36, lo +18432
//   B buf b: [73728 + b*18432] hi 64x36, lo +9216
// epilogue overlays: Ls[128][68]@0, si1@34816 si2@35328 sg1@35840 sg2@36352,
//   nflag@36864, flist@36868, xrow@40960(4KB), hrow(double)@45056(2KB),
//   vbufd(double)@47104(512B)
// =============================================================================
#define G2_SMEM 110592

__device__ __forceinline__ void g2_ldA(float4* ha, int m0, int tid, int c) {
    const int kt = c * 32;
#pragma unroll
    for (int i = 0; i < 4; i++) {
        int q = tid + i * 256;
        ha[i] = *(const float4*)(g_H + (size_t)(m0 + (q >> 3)) * D_HID + kt + (q & 7) * 4);
    }
}
__device__ __forceinline__ void g2_stsA(char* sm, const float4* ha, int tid, int b) {
    char* A = sm + b * 36864;
#pragma unroll
    for (int i = 0; i < 4; i++) {
        int q = tid + i * 256;
        int off = (q >> 3) * 144 + (q & 7) * 16;
        float4 hi, lo;
        hi.x = tf32_rn(ha[i].x); lo.x = tf32_rn(ha[i].x - hi.x);
        hi.y = tf32_rn(ha[i].y); lo.y = tf32_rn(ha[i].y - hi.y);
        hi.z = tf32_rn(ha[i].z); lo.z = tf32_rn(ha[i].z - hi.z);
        hi.w = tf32_rn(ha[i].w); lo.w = tf32_rn(ha[i].w - hi.w);
        *(float4*)(A + off)         = hi;
        *(float4*)(A + 18432 + off) = lo;
    }
}
__device__ __forceinline__ void g2_loadB(uint32_t sb, int tid, int c, int b) {
    const int kt = c * 32;
    const uint32_t B = sb + 73728 + b * 18432;
#pragma unroll
    for (int i = 0; i < 2; i++) {
        int q = tid + i * 256;
        int n = q >> 3, c4 = q & 7;
        uint32_t off = n * 144 + c4 * 16;
        cp16(B + off,        g_W2t_hi + (size_t)n * D_HID + kt + c4 * 4);
        cp16(B + 9216 + off, g_W2t_lo + (size_t)n * D_HID + kt + c4 * 4);
    }
}

__global__ __launch_bounds__(256, 1)
void gemm2_mma(const float* __restrict__ X,
               const float* __restrict__ W1,
               const float* __restrict__ b1g,
               const float* __restrict__ b2,
               float* __restrict__ out_gates,
               float* __restrict__ out_logits) {
    extern __shared__ char sm[];
    __shared__ float b2s[64];
    __shared__ float b1s2[256];
    const uint32_t sb = smem_u32(sm);
    const int tid = threadIdx.x;
    const int wid = tid >> 5, lane = tid & 31;
    const int m0 = blockIdx.x * 128;
    const int wm = wid >> 1, wn = wid & 1;       // warp tile 32x32 in 4x2 grid
    const int g = lane >> 2, t = lane & 3;

    if (tid < 64) b2s[tid] = b2[tid];
    b1s2[tid] = b1g[tid];

    float acc[2][4][4];
#pragma unroll
    for (int mt = 0; mt < 2; mt++)
#pragma unroll
        for (int nt = 0; nt < 4; nt++)
#pragma unroll
            for (int k = 0; k < 4; k++) acc[mt][nt][k] = 0.0f;

    float4 ha[4];
    g2_ldA(ha, m0, tid, 0);
    g2_stsA(sm, ha, tid, 0);
    g2_loadB(sb, tid, 0, 0);
    CP_COMMIT();

    for (int c = 0; c < 8; c++) {
        const int b = c & 1;
        if (c < 7) {
            g2_ldA(ha, m0, tid, c + 1);
            g2_loadB(sb, tid, c + 1, b ^ 1);
            CP_COMMIT();
            CP_WAIT1();
        } else {
            CP_WAIT0();
        }
        __syncthreads();

        const float* Ahi = (const float*)(sm + b * 36864);
        const float* Alo = Ahi + 4608;
        const float* Bhi = (const float*)(sm + 73728 + b * 18432);
        const float* Blo = Bhi + 2304;

#pragma unroll
        for (int ks = 0; ks < 4; ks++) {
            const int kc = ks * 8 + t;
            float ah[2][4], al[2][4];
#pragma unroll
            for (int mt = 0; mt < 2; mt++) {
                int r = wm * 32 + mt * 16 + g;
                ah[mt][0] = Ahi[r * 36 + kc];
                ah[mt][1] = Ahi[(r + 8) * 36 + kc];
                ah[mt][2] = Ahi[r * 36 + kc + 4];
                ah[mt][3] = Ahi[(r + 8) * 36 + kc + 4];
                al[mt][0] = Alo[r * 36 + kc];
                al[mt][1] = Alo[(r + 8) * 36 + kc];
                al[mt][2] = Alo[r * 36 + kc + 4];
                al[mt][3] = Alo[(r + 8) * 36 + kc + 4];
            }
#pragma unroll
            for (int nt = 0; nt < 4; nt++) {
                int n = wn * 32 + nt * 8 + g;
                float bh0 = Bhi[n * 36 + kc], bh1 = Bhi[n * 36 + kc + 4];
                float bl0 = Blo[n * 36 + kc], bl1 = Blo[n * 36 + kc + 4];
#pragma unroll
                for (int mt = 0; mt < 2; mt++) {
                    mma_tf32(acc[mt][nt], ah[mt], bh0, bh1);
                    mma_tf32(acc[mt][nt], al[mt], bh0, bh1);
                    mma_tf32(acc[mt][nt], ah[mt], bl0, bl1);
                }
            }
        }
        __syncthreads();
        if (c < 7) g2_stsA(sm, ha, tid, b ^ 1);
    }
    __syncthreads();

    // ---- epilogue overlays ----
    float*  Ls    = (float*)sm;                    // [128][68]
    int*    si1   = (int*)(sm + 34816);
    int*    si2   = (int*)(sm + 35328);
    float*  sg1   = (float*)(sm + 35840);
    float*  sg2   = (float*)(sm + 36352);
    int*    nflag = (int*)(sm + 36864);
    int*    flist = (int*)(sm + 36868);            // up to 128
    float*  xrow  = (float*)(sm + 40960);          // [1024]
    double* hrow  = (double*)(sm + 45056);         // [256]
    double* vbufd = (double*)(sm + 47104);         // [64]

    if (tid == 0) *nflag = 0;

#pragma unroll
    for (int mt = 0; mt < 2; mt++) {
        int r0 = wm * 32 + mt * 16 + g;
#pragma unroll
        for (int nt = 0; nt < 4; nt++) {
            int col = wn * 32 + nt * 8 + 2 * t;
            Ls[r0 * 68 + col]           = acc[mt][nt][0] + b2s[col];
            Ls[r0 * 68 + col + 1]       = acc[mt][nt][1] + b2s[col + 1];
            Ls[(r0 + 8) * 68 + col]     = acc[mt][nt][2] + b2s[col];
            Ls[(r0 + 8) * 68 + col + 1] = acc[mt][nt][3] + b2s[col + 1];
        }
    }
    __syncthreads();

    // per-token top-3; flag near-ties at the top-2 membership boundary
    if (tid < 128) {
        const float* Lrow = Ls + tid * 68;
        float v1 = -INFINITY, v2 = -INFINITY, v3 = -INFINITY;
        int i1 = 0, i2 = 0;
#pragma unroll
        for (int e = 0; e < N_EXP; e++) {
            float v = Lrow[e];
            if (v > v1)      { v3 = v2; v2 = v1; i2 = i1; v1 = v; i1 = e; }
            else if (v > v2) { v3 = v2; v2 = v; i2 = e; }
            else if (v > v3) { v3 = v; }
        }
        float e2  = __expf(v2 - v1);
        float inv = 1.0f / (1.0f + e2);
        si1[tid] = i1; si2[tid] = i2;
        sg1[tid] = inv; sg2[tid] = e2 * inv;
        if (v2 - v3 < 2e-4f) {
            int s = atomicAdd(nflag, 1);
            flist[s] = tid;
        }
    }
    __syncthreads();

    // fp64 full-chain repair of flagged tokens (whole CTA per token)
    const int nf = *nflag;
    for (int it = 0; it < nf; it++) {
        const int m = flist[it];
        // stage x row
        for (int i = tid; i < D_MODEL; i += 256)
            xrow[i] = X[(size_t)(m0 + m) * D_MODEL + i];
        __syncthreads();
        // h[tid] = tanh(sum_d x[d]*W1[d][tid] + b1[tid]) in fp64
        {
            double a0 = 0.0, a1 = 0.0, a2 = 0.0, a3 = 0.0;
            for (int d = 0; d < D_MODEL; d += 4) {
                a0 += (double)xrow[d]     * (double)W1[(size_t)d * D_HID + tid];
                a1 += (double)xrow[d + 1] * (double)W1[(size_t)(d + 1) * D_HID + tid];
                a2 += (double)xrow[d + 2] * (double)W1[(size_t)(d + 2) * D_HID + tid];
                a3 += (double)xrow[d + 3] * (double)W1[(size_t)(d + 3) * D_HID + tid];
            }
            hrow[tid] = tanh(((a0 + a1) + (a2 + a3)) + (double)b1s2[tid]);
        }
        __syncthreads();
        // logits in fp64: e = tid>>2, quad-partial dot + shfl reduce
        {
            const int e = tid >> 2, p = tid & 3;
            const double* hr = hrow + p * 64;
            const float*  wr = g_W2t_f32 + (size_t)e * D_HID + p * 64;
            double s = 0.0;
#pragma unroll 16
            for (int k = 0; k < 64; k++) s += hr[k] * (double)wr[k];
            s += __shfl_xor_sync(0xffffffffu, s, 1);
            s += __shfl_xor_sync(0xffffffffu, s, 2);
            if (p == 0) vbufd[e] = s + (double)b2s[e];
        }
        __syncthreads();
        if (tid == 0) {
            double v1 = -1e300, v2 = -1e300;
            int i1 = 0, i2 = 0;
#pragma unroll
            for (int ee = 0; ee < N_EXP; ee++) {
                double v = vbufd[ee];
                if (v > v1)      { v2 = v1; i2 = i1; v1 = v; i1 = ee; }
                else if (v > v2) { v2 = v; i2 = ee; }
            }
            double e2x = exp(v2 - v1);
            double inv = 1.0 / (1.0 + e2x);
            si1[m] = i1; si2[m] = i2;
            sg1[m] = (float)inv; sg2[m] = (float)(e2x * inv);
        }
        __syncthreads();
    }

    // coalesced writeback of logits + dense gates
#pragma unroll
    for (int i = 0; i < 8; i++) {
        int f = tid + i * 256;                  // 0..2047
        int row = f >> 4, c4 = (f & 15) * 4;
        float4 lv = *(const float4*)(Ls + row * 68 + c4);
        int i1 = si1[row], i2 = si2[row];
        float g1 = sg1[row], g2 = sg2[row];
        float4 gv;
        gv.x = (c4 + 0 == i1) ? g1 : ((c4 + 0 == i2) ? g2 : 0.0f);
        gv.y = (c4 + 1 == i1) ? g1 : ((c4 + 1 == i2) ? g2 : 0.0f);
        gv.z = (c4 + 2 == i1) ? g1 : ((c4 + 2 == i2) ? g2 : 0.0f);
        gv.w = (c4 + 3 == i1) ? g1 : ((c4 + 3 == i2) ? g2 : 0.0f);
        const size_t base = (size_t)(m0 + row) * N_EXP + c4;
        *(float4*)(out_logits + base) = lv;
        *(float4*)(out_gates  + base) = gv;
    }
}

// =============================================================================
extern "C" void kernel_launch(void* const* d_in, const int* in_sizes, int n_in,
                              void* d_out, int out_size) {
    const float* x  = (const float*)d_in[0];
    const float* W1 = (const float*)d_in[1];
    const float* b1 = (const float*)d_in[2];
    const float* W2 = (const float*)d_in[3];
    const float* b2 = (const float*)d_in[4];

    float* out        = (float*)d_out;
    float* out_gates  = out;
    float* out_logits = out + (size_t)out_size / 2;

    cudaFuncSetAttribute(gemm1_mma, cudaFuncAttributeMaxDynamicSharedMemorySize, G1_SMEM);
    cudaFuncSetAttribute(gemm2_mma, cudaFuncAttributeMaxDynamicSharedMemorySize, G2_SMEM);

    prep_kernel<<<(D_MODEL * D_HID + D_HID * N_EXP + 255) / 256, 256>>>(W1, W2);
    gemm1_mma<<<NTOK / 128, 256, G1_SMEM>>>(x, b1);
    gemm2_mma<<<NTOK / 128, 256, G2_SMEM>>>(x, W1, b1, b2, out_gates, out_logits);
}

// round 12
// speedup vs baseline: 3.0825x; 3.0825x over previous
#include <cuda_runtime.h>
#include <math.h>
#include <stdint.h>

#define D_MODEL 1024
#define D_HID   256
#define N_EXP   64
#define NTOK    16384

// ---------------- packed fp32x2 helpers (FFMA2 path) ----------------
__device__ __forceinline__ unsigned long long pack2(float lo, float hi) {
    unsigned long long r;
    asm("mov.b64 %0, {%1, %2};" : "=l"(r) : "f"(lo), "f"(hi));
    return r;
}
__device__ __forceinline__ void ffma2(unsigned long long& d,
                                      unsigned long long a,
                                      unsigned long long b) {
    asm("fma.rn.f32x2 %0, %1, %2, %0;" : "+l"(d) : "l"(a), "l"(b));
}
__device__ __forceinline__ float2 unpack2(unsigned long long v) {
    float2 f;
    asm("mov.b64 {%0, %1}, %2;" : "=f"(f.x), "=f"(f.y) : "l"(v));
    return f;
}
__device__ __forceinline__ void cp16(uint32_t saddr, const void* gsrc) {
    asm volatile("cp.async.cg.shared.global [%0], [%1], 16;" :: "r"(saddr), "l"(gsrc) : "memory");
}
#define CP_COMMIT() asm volatile("cp.async.commit_group;" ::: "memory")
#define CP_WAIT0()  asm volatile("cp.async.wait_group 0;" ::: "memory")
#define CP_WAIT1()  asm volatile("cp.async.wait_group 1;" ::: "memory")

__device__ __forceinline__ uint32_t smem_u32(const void* p) {
    uint32_t a;
    asm("{ .reg .u64 t; cvta.to.shared.u64 t, %1; cvt.u32.u64 %0, t; }" : "=r"(a) : "l"(p));
    return a;
}

// =============================================================================
// Fully fused gating network, pure fp32 (exact):
//   H = tanh(X@W1+b1)  -> smem (transposed Ht[k][tok])
//   logits = H@W2+b2   -> smem
//   top-2 softmax -> dense gates; outputs (gates, logits)
//
// CTA: 256 threads, 64 tokens. Mainloop tile M=64, N=256(full), BK=16,
// cp.async double-buffered W1, register-carried X with transposed STS.
//
// Dynamic smem layout (bytes):
//   [0, 67584)        Ht[256][66]  (H transposed; written after mainloop)
//                       overlay after tail: Ls[64][68] logits @0 (17408 B)
//   [67584, 71808)    A buf0: As[16][66]
//   [71808, 76032)    A buf1
//   [76032, 92672)    B buf0: Bs[16][260]
//   [92672, 109312)   B buf1
//   [76032, 108800)   overlay after mainloop: W2 half-stage Ws[128][64]
// =============================================================================
#define SM_HT  0
#define SM_A0  67584
#define SM_A1  71808
#define SM_B0  76032
#define SM_B1  92672
#define SM_W2  76032
#define SM_LS  0
#define SM_TOTAL 109312

__global__ __launch_bounds__(256, 2)
void fused_gating(const float* __restrict__ X,
                  const float* __restrict__ W1,
                  const float* __restrict__ b1,
                  const float* __restrict__ W2,
                  const float* __restrict__ b2,
                  float* __restrict__ out_gates,
                  float* __restrict__ out_logits) {
    extern __shared__ char sm[];
    __shared__ float b1s[256];
    __shared__ float b2s[64];
    __shared__ int   si1[64], si2[64];
    __shared__ float sg1[64], sg2[64];

    const uint32_t sb = smem_u32(sm);
    const int tid  = threadIdx.x;
    const int wid  = tid >> 5, lane = tid & 31;
    const int m0   = blockIdx.x * 64;
    const int wm   = wid & 1;          // M half (32 rows)
    const int wn   = wid >> 1;         // N block (64 cols)
    const int tm   = lane >> 3;        // 0..3
    const int tn   = lane & 7;         // 0..7

    b1s[tid] = b1[tid];
    if (tid < 64) b2s[tid] = b2[tid];

    // X staging indices: one float4 per thread per chunk
    const int xrow = tid >> 2;          // 0..63 (token)
    const int xk4  = (tid & 3) * 4;     // 0,4,8,12

    // accumulators: acc[p][c] = f32x2 over token rows (r, r+1), col c
    unsigned long long acc[4][8];
#pragma unroll
    for (int p = 0; p < 4; p++)
#pragma unroll
        for (int c = 0; c < 8; c++) acc[p][c] = 0ull;

    float4 xa;

    // ---- prologue: stage chunk 0 ----
    xa = *(const float4*)(X + (size_t)(m0 + xrow) * D_MODEL + xk4);
    {
        float* A = (float*)(sm + SM_A0);
        A[(xk4 + 0) * 66 + xrow] = xa.x;
        A[(xk4 + 1) * 66 + xrow] = xa.y;
        A[(xk4 + 2) * 66 + xrow] = xa.z;
        A[(xk4 + 3) * 66 + xrow] = xa.w;
    }
#pragma unroll
    for (int i = 0; i < 4; i++) {
        int q = tid + i * 256;
        int krow = q >> 6, c16 = q & 63;
        cp16(sb + SM_B0 + krow * 1040 + c16 * 16, W1 + (size_t)krow * D_HID + c16 * 4);
    }
    CP_COMMIT();

    // ---- mainloop: 64 chunks of K=16 ----
    for (int c = 0; c < 64; c++) {
        const int b = c & 1;
        if (c < 63) {
            const int kt = (c + 1) * 16;
            xa = *(const float4*)(X + (size_t)(m0 + xrow) * D_MODEL + kt + xk4);
            const uint32_t Bb = sb + (b ? SM_B0 : SM_B1);
#pragma unroll
            for (int i = 0; i < 4; i++) {
                int q = tid + i * 256;
                int krow = q >> 6, c16 = q & 63;
                cp16(Bb + krow * 1040 + c16 * 16,
                     W1 + (size_t)(kt + krow) * D_HID + c16 * 4);
            }
            CP_COMMIT();
            CP_WAIT1();
        } else {
            CP_WAIT0();
        }
        __syncthreads();

        const float* As = (const float*)(sm + (b ? SM_A1 : SM_A0));
        const float* Bs = (const float*)(sm + (b ? SM_B1 : SM_B0));

#pragma unroll
        for (int k = 0; k < 16; k++) {
            unsigned long long a[4];
#pragma unroll
            for (int p = 0; p < 4; p++)
                a[p] = *(const unsigned long long*)
                       (As + k * 66 + wm * 32 + tm * 2 + p * 8);
            float4 bv0 = *(const float4*)(Bs + k * 260 + wn * 64 + tn * 8);
            float4 bv1 = *(const float4*)(Bs + k * 260 + wn * 64 + tn * 8 + 4);
            unsigned long long bb[8];
            bb[0] = pack2(bv0.x, bv0.x); bb[1] = pack2(bv0.y, bv0.y);
            bb[2] = pack2(bv0.z, bv0.z); bb[3] = pack2(bv0.w, bv0.w);
            bb[4] = pack2(bv1.x, bv1.x); bb[5] = pack2(bv1.y, bv1.y);
            bb[6] = pack2(bv1.z, bv1.z); bb[7] = pack2(bv1.w, bv1.w);
#pragma unroll
            for (int p = 0; p < 4; p++) {
                ffma2(acc[p][0], a[p], bb[0]);
                ffma2(acc[p][1], a[p], bb[1]);
                ffma2(acc[p][2], a[p], bb[2]);
                ffma2(acc[p][3], a[p], bb[3]);
                ffma2(acc[p][4], a[p], bb[4]);
                ffma2(acc[p][5], a[p], bb[5]);
                ffma2(acc[p][6], a[p], bb[6]);
                ffma2(acc[p][7], a[p], bb[7]);
            }
        }
        __syncthreads();
        if (c < 63) {
            float* A = (float*)(sm + (b ? SM_A0 : SM_A1));
            A[(xk4 + 0) * 66 + xrow] = xa.x;
            A[(xk4 + 1) * 66 + xrow] = xa.y;
            A[(xk4 + 2) * 66 + xrow] = xa.z;
            A[(xk4 + 3) * 66 + xrow] = xa.w;
        }
    }

    // ---- overlap: start staging W2 half 0 into the dead B-buffer region ----
    // (B0's last reader finished before the final chunk's barrier.)
#pragma unroll
    for (int i = 0; i < 8; i++) {
        int q = tid + i * 256;          // 0..2047 float4s of W2[k<128][*]
        cp16(sb + SM_W2 + q * 16, W2 + (size_t)q * 4);
    }
    CP_COMMIT();

    // ---- H = tanh(acc + b1) -> Ht[k][tok] (transposed) ----
    float* Ht = (float*)(sm + SM_HT);   // [256][66]
#pragma unroll
    for (int p = 0; p < 4; p++) {
        int r = wm * 32 + tm * 2 + p * 8;           // token (even)
#pragma unroll
        for (int cc = 0; cc < 8; cc++) {
            int col = wn * 64 + tn * 8 + cc;        // hidden index
            float2 v = unpack2(acc[p][cc]);
            float2 hv;
            hv.x = tanhf(v.x + b1s[col]);
            hv.y = tanhf(v.y + b1s[col]);
            *(float2*)(Ht + col * 66 + r) = hv;
        }
    }
    CP_WAIT0();
    __syncthreads();

    // ---- tail GEMM2: logits = Ht^T @ W2 (two 32KB W2 halves in smem) ----
    // warp = 8-token group (tg), lane = expert pair (ep): e0 = 2*ep
    const int tg = wid;                 // tokens tg*8 .. tg*8+7
    const int ep = lane;                // 0..31
    const float* Ws = (const float*)(sm + SM_W2);

    unsigned long long acc2[4][2];      // [token-pair][expert-of-pair]
#pragma unroll
    for (int tp = 0; tp < 4; tp++) { acc2[tp][0] = 0ull; acc2[tp][1] = 0ull; }

#pragma unroll
    for (int half = 0; half < 2; half++) {
#pragma unroll 8
        for (int kk = 0; kk < 128; kk++) {
            const int k = half * 128 + kk;
            unsigned long long w = *(const unsigned long long*)(Ws + kk * 64 + ep * 2);
            float2 wf = unpack2(w);
            unsigned long long w0 = pack2(wf.x, wf.x);
            unsigned long long w1 = pack2(wf.y, wf.y);
#pragma unroll
            for (int tp = 0; tp < 4; tp++) {
                unsigned long long hh = *(const unsigned long long*)
                                        (Ht + k * 66 + tg * 8 + tp * 2);
                ffma2(acc2[tp][0], hh, w0);
                ffma2(acc2[tp][1], hh, w1);
            }
        }
        if (half == 0) {
            __syncthreads();            // everyone done with W2 half 0
#pragma unroll
            for (int i = 0; i < 8; i++) {
                int q = tid + i * 256;
                cp16(sb + SM_W2 + q * 16, W2 + (size_t)(2048 + q) * 4);
            }
            CP_COMMIT();
            CP_WAIT0();
            __syncthreads();
        }
    }
    __syncthreads();                    // all Ht reads done; safe to overlay Ls

    // ---- stage logits (+b2) into Ls[64][68] ----
    float* Ls = (float*)(sm + SM_LS);
#pragma unroll
    for (int tp = 0; tp < 4; tp++) {
        int t0 = tg * 8 + tp * 2;
        int e0 = ep * 2;
        float2 v0 = unpack2(acc2[tp][0]);   // expert e0, tokens (t0, t0+1)
        float2 v1 = unpack2(acc2[tp][1]);   // expert e0+1
        Ls[t0 * 68 + e0]           = v0.x + b2s[e0];
        Ls[(t0 + 1) * 68 + e0]     = v0.y + b2s[e0];
        Ls[t0 * 68 + e0 + 1]       = v1.x + b2s[e0 + 1];
        Ls[(t0 + 1) * 68 + e0 + 1] = v1.y + b2s[e0 + 1];
    }
    __syncthreads();

    // ---- per-token top-2 + softmax-of-2 ----
    if (tid < 64) {
        const float* Lrow = Ls + tid * 68;
        float v1 = -INFINITY, v2 = -INFINITY;
        int i1 = 0, i2 = 0;
#pragma unroll
        for (int e = 0; e < N_EXP; e++) {
            float v = Lrow[e];
            if (v > v1)      { v2 = v1; i2 = i1; v1 = v; i1 = e; }
            else if (v > v2) { v2 = v; i2 = e; }
        }
        float e2  = __expf(v2 - v1);
        float inv = 1.0f / (1.0f + e2);
        si1[tid] = i1; si2[tid] = i2;
        sg1[tid] = inv; sg2[tid] = e2 * inv;
    }
    __syncthreads();

    // ---- coalesced writeback: logits + dense gates ----
#pragma unroll
    for (int i = 0; i < 4; i++) {
        int f = tid + i * 256;                // 0..1023
        int row = f >> 4, c4 = (f & 15) * 4;
        float4 lv = *(const float4*)(Ls + row * 68 + c4);
        int i1 = si1[row], i2 = si2[row];
        float g1 = sg1[row], g2 = sg2[row];
        float4 gv;
        gv.x = (c4 + 0 == i1) ? g1 : ((c4 + 0 == i2) ? g2 : 0.0f);
        gv.y = (c4 + 1 == i1) ? g1 : ((c4 + 1 == i2) ? g2 : 0.0f);
        gv.z = (c4 + 2 == i1) ? g1 : ((c4 + 2 == i2) ? g2 : 0.0f);
        gv.w = (c4 + 3 == i1) ? g1 : ((c4 + 3 == i2) ? g2 : 0.0f);
        const size_t base = (size_t)(m0 + row) * N_EXP + c4;
        *(float4*)(out_logits + base) = lv;
        *(float4*)(out_gates  + base) = gv;
    }
}

// =============================================================================
extern "C" void kernel_launch(void* const* d_in, const int* in_sizes, int n_in,
                              void* d_out, int out_size) {
    const float* x  = (const float*)d_in[0];   // [4,4096,1024]
    const float* W1 = (const float*)d_in[1];   // [1024,256]
    const float* b1 = (const float*)d_in[2];   // [256]
    const float* W2 = (const float*)d_in[3];   // [256,64]
    const float* b2 = (const float*)d_in[4];   // [64]

    float* out        = (float*)d_out;
    float* out_gates  = out;
    float* out_logits = out + (size_t)out_size / 2;

    cudaFuncSetAttribute(fused_gating, cudaFuncAttributeMaxDynamicSharedMemorySize,
                         SM_TOTAL);
    fused_gating<<<NTOK / 64, 256, SM_TOTAL>>>(x, W1, b1, W2, b2,
                                               out_gates, out_logits);
}